// round 2
// baseline (speedup 1.0000x reference)
#include <cuda_runtime.h>
#include <cuda_bf16.h>
#include <cstdint>

#define N_NODES 50000
#define D_FEAT  64
#define H_FEAT  128

// Scratch accumulator: acc = (1+eps)*x + neighbor-sum  (12.8 MB)
__device__ float g_acc[(size_t)N_NODES * D_FEAT];

// ---------------------------------------------------------------------------
// Kernel 1: acc[i] = (1+eps) * x[i]   (vectorized float4)
// ---------------------------------------------------------------------------
__global__ void init_acc_kernel(const float* __restrict__ x,
                                const float* __restrict__ eps,
                                int total4) {
    int i = blockIdx.x * blockDim.x + threadIdx.x;
    if (i >= total4) return;
    float s = 1.0f + eps[0];
    float4 v = reinterpret_cast<const float4*>(x)[i];
    v.x *= s; v.y *= s; v.z *= s; v.w *= s;
    reinterpret_cast<float4*>(g_acc)[i] = v;
}

// ---------------------------------------------------------------------------
// Kernel 2: edge scatter. 16 lanes per edge; lane c handles float4 chunk c.
//   acc[src] += x[dst];  acc[dst] += x[src]   (red.global.add.v4.f32)
// edge_index stored as int32 by the harness.
// ---------------------------------------------------------------------------
__global__ void scatter_kernel(const float* __restrict__ x,
                               const int* __restrict__ ei,
                               int E, int N) {
    int t = blockIdx.x * blockDim.x + threadIdx.x;
    int e = t >> 4;
    if (e >= E) return;
    int c = (t & 15) << 2;   // float offset of this lane's float4 chunk

    int s = ei[e];
    int d = ei[(size_t)E + e];
    if ((unsigned)s >= (unsigned)N || (unsigned)d >= (unsigned)N) return;

    const float4 vs = *reinterpret_cast<const float4*>(x + (size_t)s * D_FEAT + c);
    const float4 vd = *reinterpret_cast<const float4*>(x + (size_t)d * D_FEAT + c);

    float* as = g_acc + (size_t)s * D_FEAT + c;
    float* ad = g_acc + (size_t)d * D_FEAT + c;

    asm volatile("red.global.add.v4.f32 [%0], {%1, %2, %3, %4};"
                 :: "l"(as), "f"(vd.x), "f"(vd.y), "f"(vd.z), "f"(vd.w)
                 : "memory");
    asm volatile("red.global.add.v4.f32 [%0], {%1, %2, %3, %4};"
                 :: "l"(ad), "f"(vs.x), "f"(vs.y), "f"(vs.z), "f"(vs.w)
                 : "memory");
}

// ---------------------------------------------------------------------------
// Kernel 3: fused GIN MLP.  y = relu(acc @ W1 + b1) @ W2 + b2
// 32-node tile per block, 256 threads.
// ---------------------------------------------------------------------------
#define NT 32
#define VP 33   // Vt/Ht row padding (floats) to dodge bank conflicts

__global__ __launch_bounds__(256, 4)
void mlp_kernel(const float* __restrict__ W1, const float* __restrict__ b1,
                const float* __restrict__ W2, const float* __restrict__ b2,
                float* __restrict__ out, int N) {
    __shared__ float Vt[D_FEAT * VP];   // Vt[k][n]
    __shared__ float Ht[H_FEAT * VP];   // Ht[j][n]

    const int t  = threadIdx.x;
    const int n0 = blockIdx.x * NT;

    // ---- stage V (transposed) ----
    for (int idx = t; idx < NT * D_FEAT; idx += 256) {
        int n = idx >> 6;        // node within tile
        int k = idx & 63;        // feature
        int node = n0 + n;
        Vt[k * VP + n] = (node < N) ? g_acc[(size_t)node * D_FEAT + k] : 0.0f;
    }
    __syncthreads();

    // ---- GEMM1: H[NT][128] = relu(V @ W1 + b1) ----
    {
        const int tx = t & 31;       // j group: 32 * 4 = 128 columns
        const int ty = t >> 5;       // node group: 8 * 4 = 32 nodes
        const int j4 = tx * 4;
        const int nb = ty * 4;

        float a[4][4];
        float4 bb = *reinterpret_cast<const float4*>(b1 + j4);
        #pragma unroll
        for (int i = 0; i < 4; i++) {
            a[i][0] = bb.x; a[i][1] = bb.y; a[i][2] = bb.z; a[i][3] = bb.w;
        }

        #pragma unroll 8
        for (int k = 0; k < D_FEAT; k++) {
            float4 w = *reinterpret_cast<const float4*>(W1 + k * H_FEAT + j4);
            float v0 = Vt[k * VP + nb + 0];
            float v1 = Vt[k * VP + nb + 1];
            float v2 = Vt[k * VP + nb + 2];
            float v3 = Vt[k * VP + nb + 3];
            a[0][0] = fmaf(v0, w.x, a[0][0]); a[0][1] = fmaf(v0, w.y, a[0][1]);
            a[0][2] = fmaf(v0, w.z, a[0][2]); a[0][3] = fmaf(v0, w.w, a[0][3]);
            a[1][0] = fmaf(v1, w.x, a[1][0]); a[1][1] = fmaf(v1, w.y, a[1][1]);
            a[1][2] = fmaf(v1, w.z, a[1][2]); a[1][3] = fmaf(v1, w.w, a[1][3]);
            a[2][0] = fmaf(v2, w.x, a[2][0]); a[2][1] = fmaf(v2, w.y, a[2][1]);
            a[2][2] = fmaf(v2, w.z, a[2][2]); a[2][3] = fmaf(v2, w.w, a[2][3]);
            a[3][0] = fmaf(v3, w.x, a[3][0]); a[3][1] = fmaf(v3, w.y, a[3][1]);
            a[3][2] = fmaf(v3, w.z, a[3][2]); a[3][3] = fmaf(v3, w.w, a[3][3]);
        }

        #pragma unroll
        for (int jj = 0; jj < 4; jj++)
            #pragma unroll
            for (int i = 0; i < 4; i++)
                Ht[(j4 + jj) * VP + nb + i] = fmaxf(a[i][jj], 0.0f);
    }
    __syncthreads();

    // ---- GEMM2: Y[NT][64] = H @ W2 + b2 ----
    {
        const int tx = t & 15;       // d group: 16 * 4 = 64 columns
        const int ty = t >> 4;       // node group: 16 * 2 = 32 nodes
        const int d4 = tx * 4;
        const int nb = ty * 2;

        float a[2][4];
        float4 bb = *reinterpret_cast<const float4*>(b2 + d4);
        a[0][0] = bb.x; a[0][1] = bb.y; a[0][2] = bb.z; a[0][3] = bb.w;
        a[1][0] = bb.x; a[1][1] = bb.y; a[1][2] = bb.z; a[1][3] = bb.w;

        #pragma unroll 8
        for (int j = 0; j < H_FEAT; j++) {
            float4 w = *reinterpret_cast<const float4*>(W2 + j * D_FEAT + d4);
            float v0 = Ht[j * VP + nb + 0];
            float v1 = Ht[j * VP + nb + 1];
            a[0][0] = fmaf(v0, w.x, a[0][0]); a[0][1] = fmaf(v0, w.y, a[0][1]);
            a[0][2] = fmaf(v0, w.z, a[0][2]); a[0][3] = fmaf(v0, w.w, a[0][3]);
            a[1][0] = fmaf(v1, w.x, a[1][0]); a[1][1] = fmaf(v1, w.y, a[1][1]);
            a[1][2] = fmaf(v1, w.z, a[1][2]); a[1][3] = fmaf(v1, w.w, a[1][3]);
        }

        #pragma unroll
        for (int i = 0; i < 2; i++) {
            int node = n0 + nb + i;
            if (node < N) {
                float4 y = make_float4(a[i][0], a[i][1], a[i][2], a[i][3]);
                *reinterpret_cast<float4*>(out + (size_t)node * D_FEAT + d4) = y;
            }
        }
    }
}

// ---------------------------------------------------------------------------
// Launch
// ---------------------------------------------------------------------------
extern "C" void kernel_launch(void* const* d_in, const int* in_sizes, int n_in,
                              void* d_out, int out_size) {
    const float* x   = (const float*)d_in[0];
    const float* W1  = (const float*)d_in[1];
    const float* b1  = (const float*)d_in[2];
    const float* W2  = (const float*)d_in[3];
    const float* b2  = (const float*)d_in[4];
    const float* eps = (const float*)d_in[5];
    const int*   ei  = (const int*)d_in[6];     // edge_index as int32
    float* out = (float*)d_out;

    const int N = in_sizes[0] / D_FEAT;     // 50000
    const int E = in_sizes[6] / 2;          // 800000

    // 1) acc = (1+eps)*x
    int total4 = N * D_FEAT / 4;
    init_acc_kernel<<<(total4 + 255) / 256, 256>>>(x, eps, total4);

    // 2) edge scatter (16 lanes / edge)
    long long threads = (long long)E * 16;
    int blocks = (int)((threads + 255) / 256);
    scatter_kernel<<<blocks, 256>>>(x, ei, E, N);

    // 3) fused MLP
    mlp_kernel<<<(N + NT - 1) / NT, 256>>>(W1, b1, W2, b2, out, N);
}